// round 10
// baseline (speedup 1.0000x reference)
#include <cuda_runtime.h>
#include <math.h>

// Problem constants (fixed shapes from setup_inputs)
#define LL 4
#define BB 8
#define NS 1200
#define NL 128
#define CC 768
#define HH 448
#define WW 448
#define GS 56            // H/8   (grid cols, small)
#define GL 16            // H/28  (grid cols, large)
#define VS (GS*GS)       // 3136
#define VL (GL*GL)       // 256
#define LB (LL*BB)       // 32
#define ROWS_PER_BLK 32          // 8 warps x 4 rows
#define NBS ((NS + ROWS_PER_BLK - 1) / ROWS_PER_BLK)   // 38 (tail guarded)
#define NBL (NL / ROWS_PER_BLK)                        // 4
#define GDX (NBS + NBL)          // 42
#define NSAMP (BB*VS + BB*VL)    // 27136 mask samples
#define SAMP_PER_BLK 21          // ceil(27136 / (42*32))
#define STATS_BLOCKS (2*LB)      // 64

// Scratch (no allocations -> __device__ globals). Device-code refs only.
__device__ float g_dist_s[LB*NS];
__device__ float g_dist_l[LB*NL];
__device__ unsigned char g_nz_s[LL*NS*8];   // [l][n][b] nonzero flags
__device__ unsigned char g_nz_l[LL*NL*8];
__device__ unsigned char g_valid_s[BB*VS];
__device__ unsigned char g_valid_l[BB*VL];
__device__ float g_sp[2*LB];
__device__ float g_sn[2*LB];
__device__ int   g_cp[2*LB];
__device__ int   g_cn[2*LB];
__device__ unsigned g_done;

// ---------------------------------------------------------------------------
// 1) Main HBM-bound pass (both scales, one launch).
//    4 independent row streams per warp -> >=4 outstanding float4 LDGs per
//    thread per k-step. Anchor slice in registers.
//    Side duties: f_k mask sampling; one block resets the done counter.
// ---------------------------------------------------------------------------
__global__ void k_dist(const float* __restrict__ sel_s,
                       const float* __restrict__ ker_s,
                       const float* __restrict__ sel_l,
                       const float* __restrict__ ker_l,
                       const float* __restrict__ fk) {
    __shared__ float sa[CC];
    int lb = blockIdx.y;   // l*B + b
    int l  = lb / BB;
    int scale = (blockIdx.x >= NBS) ? 1 : 0;
    int bx = scale ? (blockIdx.x - NBS) : blockIdx.x;
    int N = scale ? NL : NS;
    const float* sel = scale ? sel_l : sel_s;
    const float* ker = scale ? ker_l : ker_s;

    // --- side duty: f_k mask sampling (overlapped with main pass) ---
    {
        int bid = blockIdx.y * GDX + blockIdx.x;
        int s = bid * SAMP_PER_BLK + threadIdx.x;
        if (threadIdx.x < SAMP_PER_BLK && s < NSAMP) {
            if (s < BB*VS) {
                int b = s / VS, p = s % VS;
                int i = p / GS, j = p % GS;
                g_valid_s[s] = fk[(size_t)b*HH*WW + (size_t)i*8*WW + j*8] > 0.f;
            } else {
                int u = s - BB*VS;
                int b = u / VL, p = u % VL;
                int i = p / GL, j = p % GL;
                g_valid_l[u] = fk[(size_t)b*HH*WW + (size_t)i*28*WW + j*28] > 0.f;
            }
        }
        if (bid == 0 && threadIdx.x == 32) g_done = 0u;
    }

    const float* a = ker + (size_t)lb * CC;   // kernel (L,B,C,1) -> contiguous C
    for (int i = threadIdx.x; i < CC; i += blockDim.x) sa[i] = a[i];
    __syncthreads();

    int warp = threadIdx.x >> 5;
    int lane = threadIdx.x & 31;

    // anchor slice -> registers (reused for all 4 rows)
    const float4* av = (const float4*)sa;
    float4 aa[CC/128];
#pragma unroll
    for (int k = 0; k < CC/128; k++) aa[k] = av[k*32 + lane];

    // 4 row streams: n, n+8, n+16, n+24 (clamped loads for the tail block)
    int n0 = bx * ROWS_PER_BLK + warp;
    const float4* rowp[4];
    bool live[4];
#pragma unroll
    for (int r = 0; r < 4; r++) {
        int n = n0 + r*8;
        live[r] = (n < N);
        int nc = live[r] ? n : (N - 1);
        rowp[r] = (const float4*)(sel + ((size_t)lb * N + nc) * CC);
    }

    float s2[4]  = {0.f, 0.f, 0.f, 0.f};
    float sab[4] = {0.f, 0.f, 0.f, 0.f};
#pragma unroll
    for (int k = 0; k < CC/128; k++) {   // 6 iterations; 4 independent LDG.128s
        float4 v[4];
#pragma unroll
        for (int r = 0; r < 4; r++) v[r] = rowp[r][k*32 + lane];
        float4 A = aa[k];
#pragma unroll
        for (int r = 0; r < 4; r++) {
            float d0 = A.x - v[r].x, d1 = A.y - v[r].y;
            float d2 = A.z - v[r].z, d3 = A.w - v[r].w;
            s2[r] = fmaf(d0, d0, s2[r]); s2[r] = fmaf(d1, d1, s2[r]);
            s2[r] = fmaf(d2, d2, s2[r]); s2[r] = fmaf(d3, d3, s2[r]);
            sab[r] += fabsf(v[r].x) + fabsf(v[r].y) + fabsf(v[r].z) + fabsf(v[r].w);
        }
    }
#pragma unroll
    for (int r = 0; r < 4; r++) {
#pragma unroll
        for (int o = 16; o; o >>= 1) {
            s2[r]  += __shfl_xor_sync(0xFFFFFFFFu, s2[r],  o);
            sab[r] += __shfl_xor_sync(0xFFFFFFFFu, sab[r], o);
        }
    }
    if (lane == 0) {
        int b = lb % BB;
#pragma unroll
        for (int r = 0; r < 4; r++) {
            if (!live[r]) continue;
            int n = n0 + r*8;
            unsigned char nzb = (sab[r] != 0.f) ? 1 : 0;
            if (scale == 0) {
                g_dist_s[(size_t)lb * NS + n] = sqrtf(s2[r]);
                g_nz_s[((size_t)l*NS + n)*8 + b] = nzb;
            } else {
                g_dist_l[(size_t)lb * NL + n] = sqrtf(s2[r]);
                g_nz_l[((size_t)l*NL + n)*8 + b] = nzb;
            }
        }
    }
}

// ---------------------------------------------------------------------------
// 2) Masked accumulation, one block per gb (64 blocks), MLP-5 unrolled loads,
//    deterministic block reduce, direct result write, fused last-block
//    finalization.
// ---------------------------------------------------------------------------
__global__ void k_stats(const int* __restrict__ idx_s,
                        const int* __restrict__ idx_l,
                        float* __restrict__ out) {
    int gb = blockIdx.x;
    int scale = gb / LB;      // 0 = s, 1 = l
    int lb = gb % LB;
    int l = lb / BB, b = lb % BB;
    int N = scale ? NL : NS;
    int V = scale ? VL : VS;
    const float* dist = scale ? g_dist_l : g_dist_s;
    const unsigned char* nz = scale ? g_nz_l : g_nz_s;
    const unsigned char* valid = scale ? g_valid_l : g_valid_s;
    const int* idx = scale ? idx_l : idx_s;

    unsigned long long w[5];
    int   id[5];
    float d [5];
#pragma unroll
    for (int k = 0; k < 5; k++) {
        int n = k * 256 + threadIdx.x;
        bool ok = n < N;
        w[k]  = ok ? *(const unsigned long long*)(nz + ((size_t)l*N + n)*8) : 0ull;
        id[k] = ok ? idx[((size_t)l*BB + b)*N + n] : 0;
        d[k]  = ok ? dist[(size_t)lb*N + n] : 0.f;
    }

    float sp = 0.f, sn = 0.f;
    int   cp = 0,   cn = 0;
#pragma unroll
    for (int k = 0; k < 5; k++) {
        if (w[k] != 0ull) {
            bool mem = valid[b*V + id[k]] != 0;
            if (mem) { sp += d[k]; cp++; } else { sn += d[k]; cn++; }
        }
    }

#pragma unroll
    for (int o = 16; o; o >>= 1) {
        sp += __shfl_xor_sync(0xFFFFFFFFu, sp, o);
        sn += __shfl_xor_sync(0xFFFFFFFFu, sn, o);
        cp += __shfl_xor_sync(0xFFFFFFFFu, cp, o);
        cn += __shfl_xor_sync(0xFFFFFFFFu, cn, o);
    }
    __shared__ float rsp[8], rsn[8];
    __shared__ int   rcp[8], rcn[8];
    int warp = threadIdx.x >> 5;
    if ((threadIdx.x & 31) == 0) { rsp[warp]=sp; rsn[warp]=sn; rcp[warp]=cp; rcn[warp]=cn; }
    __syncthreads();
    if (threadIdx.x == 0) {
        float tsp = 0.f, tsn = 0.f; int tcp = 0, tcn = 0;
#pragma unroll
        for (int v2 = 0; v2 < 8; v2++) {
            tsp += rsp[v2]; tsn += rsn[v2]; tcp += rcp[v2]; tcn += rcn[v2];
        }
        g_sp[gb] = tsp; g_sn[gb] = tsn; g_cp[gb] = tcp; g_cn[gb] = tcn;
    }

    // ---- last-block finalization ----
    __shared__ bool is_last;
    __syncthreads();
    if (threadIdx.x == 0) {
        __threadfence();
        unsigned prev = atomicAdd(&g_done, 1u);
        is_last = (prev == STATS_BLOCKS - 1);
    }
    __syncthreads();
    if (!is_last) return;
    __threadfence();

    __shared__ float s_loss[2*LB];
    __shared__ int   s_act [2*LB];
    int t = threadIdx.x;
    if (t < 2*LB) {
        int tcp = g_cp[t], tcn = g_cn[t];
        float ap = g_sp[t] / (float)(tcp > 1 ? tcp : 1);
        float an = g_sn[t] / (float)(tcn > 1 ? tcn : 1);
        float x = ap - an;
        float loss = (x > 0.f) ? (x + log1pf(expf(-x))) : log1pf(expf(x));
        s_loss[t] = loss;
        s_act[t]  = (tcp > 0 && tcn > 0) ? 1 : 0;
    }
    __syncthreads();
    if (t < 64) {
        float v = 0.f; int c = 0;
        if (t < LB) {                       // small scale: act_s
            if (s_act[t]) { v = s_loss[t]; c = 1; }
        } else {                            // large scale: act_l & act_s
            if (s_act[t] && s_act[t - LB]) { v = s_loss[t]; c = 1; }
        }
#pragma unroll
        for (int o = 16; o; o >>= 1) {
            v += __shfl_xor_sync(0xFFFFFFFFu, v, o);
            c += __shfl_xor_sync(0xFFFFFFFFu, c, o);
        }
        __shared__ float sv[2]; __shared__ int sc[2];
        int w2 = t >> 5;
        if ((t & 31) == 0) { sv[w2] = v; sc[w2] = c; }
        __syncthreads();
        if (t == 0) {
            float total = sv[0] + sv[1];
            int times = sc[0] + sc[1];
            out[0] = (times > 0) ? total / (float)times : 0.f;
        }
    }
}

// ---------------------------------------------------------------------------
extern "C" void kernel_launch(void* const* d_in, const int* in_sizes, int n_in,
                              void* d_out, int out_size) {
    const float* sel_s = (const float*)d_in[0];
    const int*   idx_s = (const int*)  d_in[1];
    const float* sel_l = (const float*)d_in[2];
    const int*   idx_l = (const int*)  d_in[3];
    const float* ker_s = (const float*)d_in[4];
    const float* ker_l = (const float*)d_in[5];
    const float* fk    = (const float*)d_in[6];

    dim3 gd(GDX, LB);   // (42, 32) = 1344 blocks
    k_dist<<<gd, 256>>>(sel_s, ker_s, sel_l, ker_l, fk);

    k_stats<<<STATS_BLOCKS, 256>>>(idx_s, idx_l, (float*)d_out);
}